// round 2
// baseline (speedup 1.0000x reference)
#include <cuda_runtime.h>
#include <cuda_bf16.h>
#include <math.h>

// Problem dims (fixed by the dataset)
#define T_  4
#define B_  64
#define N_  196
#define P_  768
#define D_  256
#define M_  (T_ * B_ * N_)        // 50176
#define BND (B_ * N_ * D_)        // 3211264
#define NBLK_M (M_ / 128)         // 392

// ---------------- scratch (allocation-free per harness rules) ----------------
__device__ float g_H[(size_t)M_ * D_];       // GEMM output [M, D] ~ 51.4 MB
__device__ float g_psum[NBLK_M * D_];
__device__ float g_psq [NBLK_M * D_];
__device__ float g_mean[D_];
__device__ float g_invstd[D_];
__device__ float g_pe[N_ * D_];

// ---------------- tAPE positional encoding --------------------------------
// Replicates: c = -log(10000)/256 (f64->f32); t = f32(2i)*c; div = exp(t);
// arg = (f32(n)*div) * f32(256/196); pe[n,2i]=sin(arg), pe[n,2i+1]=cos(arg).
// sin/cos/exp evaluated in double of the fp32 args for max fidelity.
__global__ void pe_kernel() {
    int n = blockIdx.x;          // 0..195
    int i = threadIdx.x;         // 0..127
    const float c = (float)(-9.210340371976184 / 256.0);
    float t = (float)(2 * i) * c;
    float div = (float)exp((double)t);
    float arg = ((float)n * div) * (float)(256.0 / 196.0);
    g_pe[n * D_ + 2 * i]     = (float)sin((double)arg);
    g_pe[n * D_ + 2 * i + 1] = (float)cos((double)arg);
}

// ---------------- fp32 GEMM: H[m,d] = sum_p x[m,p] * W[d,p] ----------------
// Block tile 128(M) x 128(D), K-chunk 16, 256 threads, 8x8 per thread.
__global__ void __launch_bounds__(256) gemm_kernel(const float* __restrict__ A,
                                                   const float* __restrict__ W) {
    __shared__ float As[16][128];
    __shared__ float Bs[16][128];

    const int m0 = blockIdx.x * 128;
    const int n0 = blockIdx.y * 128;
    const int tid = threadIdx.x;
    const int tx = tid & 15;          // 0..15 -> d
    const int ty = tid >> 4;          // 0..15 -> m
    const int lr = tid >> 2;          // 0..63 load row
    const int lk = (tid & 3) * 4;     // 0,4,8,12 load k offset

    float acc[8][8];
#pragma unroll
    for (int i = 0; i < 8; i++)
#pragma unroll
        for (int j = 0; j < 8; j++) acc[i][j] = 0.f;

    for (int k0 = 0; k0 < P_; k0 += 16) {
#pragma unroll
        for (int p = 0; p < 2; p++) {
            int m = lr + p * 64;
            float4 v = *(const float4*)&A[(size_t)(m0 + m) * P_ + k0 + lk];
            As[lk + 0][m] = v.x; As[lk + 1][m] = v.y;
            As[lk + 2][m] = v.z; As[lk + 3][m] = v.w;
        }
#pragma unroll
        for (int p = 0; p < 2; p++) {
            int n = lr + p * 64;
            float4 v = *(const float4*)&W[(size_t)(n0 + n) * P_ + k0 + lk];
            Bs[lk + 0][n] = v.x; Bs[lk + 1][n] = v.y;
            Bs[lk + 2][n] = v.z; Bs[lk + 3][n] = v.w;
        }
        __syncthreads();
#pragma unroll
        for (int k = 0; k < 16; k++) {
            float a[8], b[8];
            *(float4*)&a[0] = *(const float4*)&As[k][ty * 8];
            *(float4*)&a[4] = *(const float4*)&As[k][ty * 8 + 4];
            *(float4*)&b[0] = *(const float4*)&Bs[k][tx * 8];
            *(float4*)&b[4] = *(const float4*)&Bs[k][tx * 8 + 4];
#pragma unroll
            for (int i = 0; i < 8; i++)
#pragma unroll
                for (int j = 0; j < 8; j++) acc[i][j] = fmaf(a[i], b[j], acc[i][j]);
        }
        __syncthreads();
    }

#pragma unroll
    for (int i = 0; i < 8; i++) {
        size_t row = (size_t)(m0 + ty * 8 + i) * D_ + n0 + tx * 8;
        *(float4*)&g_H[row]     = *(float4*)&acc[i][0];
        *(float4*)&g_H[row + 4] = *(float4*)&acc[i][4];
    }
}

// ---------------- BN stats: deterministic two-stage reduction --------------
__global__ void bn_partial_kernel() {
    int d = threadIdx.x;                 // 0..255
    int blk = blockIdx.x;                // 0..391
    const float* p = g_H + (size_t)blk * 128 * D_ + d;
    float s = 0.f, q = 0.f;
#pragma unroll 4
    for (int r = 0; r < 128; r++) {
        float v = p[(size_t)r * D_];
        s += v;
        q += v * v;
    }
    g_psum[blk * D_ + d] = s;
    g_psq [blk * D_ + d] = q;
}

__global__ void bn_final_kernel() {
    int d = threadIdx.x;
    double s = 0.0, q = 0.0;
    for (int b = 0; b < NBLK_M; b++) {
        s += (double)g_psum[b * D_ + d];
        q += (double)g_psq [b * D_ + d];
    }
    double m = s / (double)M_;
    double var = q / (double)M_ - m * m;
    g_mean[d]   = (float)m;
    g_invstd[d] = (float)(1.0 / sqrt(var + 1e-5));
}

// ---------------- BN + LIF + PE + LIF fused over T -------------------------
__global__ void lif_kernel(const float* __restrict__ gamma,
                           const float* __restrict__ beta,
                           float* __restrict__ out) {
    int e = blockIdx.x * blockDim.x + threadIdx.x;
    if (e >= BND) return;
    int d = e & (D_ - 1);
    int bn = e >> 8;
    int n = bn % N_;

    float mu = g_mean[d];
    float is = g_invstd[d];
    float g  = gamma[d];
    float bt = beta[d];
    float p  = g_pe[n * D_ + d];

    float v1 = 0.f, v2 = 0.f;
#pragma unroll
    for (int t = 0; t < T_; t++) {
        float h = g_H[(size_t)t * BND + e];
        h = (h - mu) * is;
        h = h * g + bt;
        // LIF 1: v += (x - v)/2 ; spike ; hard reset
        v1 = v1 + (h - v1) * 0.5f;
        float s1 = ((v1 - 0.5f) >= 0.f) ? 1.f : 0.f;
        v1 = v1 * (1.f - s1);
        // tAPE + LIF 2
        float x2 = s1 + p;
        v2 = v2 + (x2 - v2) * 0.5f;
        float s2 = ((v2 - 0.5f) >= 0.f) ? 1.f : 0.f;
        v2 = v2 * (1.f - s2);
        out[(size_t)t * BND + e] = s2;
    }
}

// ---------------- launch ----------------------------------------------------
extern "C" void kernel_launch(void* const* d_in, const int* in_sizes, int n_in,
                              void* d_out, int out_size) {
    const float* x     = (const float*)d_in[0];   // [T,B,N,P]
    const float* W     = (const float*)d_in[1];   // [D,P]
    const float* gamma = (const float*)d_in[2];   // [D]
    const float* beta  = (const float*)d_in[3];   // [D]
    float* out = (float*)d_out;                   // [T,B,N,D]

    pe_kernel<<<N_, 128>>>();
    gemm_kernel<<<dim3(NBLK_M, 2), 256>>>(x, W);
    bn_partial_kernel<<<NBLK_M, 256>>>();
    bn_final_kernel<<<1, D_>>>();
    lif_kernel<<<BND / 256, 256>>>(gamma, beta, out);
}

// round 6
// speedup vs baseline: 1.3824x; 1.3824x over previous
#include <cuda_runtime.h>
#include <cuda_bf16.h>
#include <cstdint>
#include <math.h>

// Problem dims (fixed by the dataset)
#define T_  4
#define B_  64
#define N_  196
#define P_  768
#define D_  256
#define M_  (T_ * B_ * N_)        // 50176
#define BND (B_ * N_ * D_)        // 3211264
#define NBLK_M (M_ / 128)         // 392

static constexpr size_t SA_ELEMS = (size_t)M_ * P_;   // 38,535,168
static constexpr size_t SB_ELEMS = (size_t)D_ * P_;   // 196,608

// ---------------- scratch (allocation-free per harness rules) ----------------
__device__ float g_H[(size_t)M_ * D_];                 // GEMM output [M, D]
__device__ __nv_bfloat16 g_SA[3][SA_ELEMS];            // bf16x3 splits of x
__device__ __nv_bfloat16 g_SB[3][SB_ELEMS];            // bf16x3 splits of W
__device__ float g_psum[NBLK_M * D_];
__device__ float g_psq [NBLK_M * D_];
__device__ float g_mean[D_];
__device__ float g_invstd[D_];
__device__ float g_pe[N_ * D_];

// ---------------- tAPE positional encoding --------------------------------
__global__ void pe_kernel() {
    int n = blockIdx.x;          // 0..195
    int i = threadIdx.x;         // 0..127
    const float c = (float)(-9.210340371976184 / 256.0);
    float t = (float)(2 * i) * c;
    float div = (float)exp((double)t);
    float arg = ((float)n * div) * (float)(256.0 / 196.0);
    g_pe[n * D_ + 2 * i]     = (float)sin((double)arg);
    g_pe[n * D_ + 2 * i + 1] = (float)cos((double)arg);
}

// ---------------- fp32 -> bf16 x3 error-free split --------------------------
__device__ __forceinline__ unsigned pack2(unsigned short lo, unsigned short hi) {
    return (unsigned)lo | ((unsigned)hi << 16);
}

__device__ __forceinline__ void split4(const float4 v,
                                       __nv_bfloat16* p1, __nv_bfloat16* p2, __nv_bfloat16* p3) {
    float xs[4] = {v.x, v.y, v.z, v.w};
    unsigned short a1[4], a2[4], a3[4];
#pragma unroll
    for (int j = 0; j < 4; j++) {
        float x = xs[j];
        __nv_bfloat16 b1 = __float2bfloat16_rn(x);
        float r = x - __bfloat162float(b1);          // exact
        __nv_bfloat16 b2 = __float2bfloat16_rn(r);
        float r2 = r - __bfloat162float(b2);         // exact
        __nv_bfloat16 b3 = __float2bfloat16_rn(r2);
        a1[j] = *(unsigned short*)&b1;
        a2[j] = *(unsigned short*)&b2;
        a3[j] = *(unsigned short*)&b3;
    }
    uint2 u1 = {pack2(a1[0], a1[1]), pack2(a1[2], a1[3])};
    uint2 u2 = {pack2(a2[0], a2[1]), pack2(a2[2], a2[3])};
    uint2 u3 = {pack2(a3[0], a3[1]), pack2(a3[2], a3[3])};
    *(uint2*)p1 = u1;
    *(uint2*)p2 = u2;
    *(uint2*)p3 = u3;
}

__global__ void splitA_kernel(const float* __restrict__ x) {
    size_t i = ((size_t)blockIdx.x * 256 + threadIdx.x) * 4;
    float4 v = *(const float4*)(x + i);
    split4(v, &g_SA[0][i], &g_SA[1][i], &g_SA[2][i]);
}

__global__ void splitB_kernel(const float* __restrict__ w) {
    size_t i = ((size_t)blockIdx.x * 256 + threadIdx.x) * 4;
    float4 v = *(const float4*)(w + i);
    split4(v, &g_SB[0][i], &g_SB[1][i], &g_SB[2][i]);
}

// ---------------- bf16x3 tensor-core GEMM ----------------------------------
// H[m,d] = sum_p x[m,p] * W[d,p], fp32 accuracy via 6 bf16 pairings.
#define LDSM4(R, addr) \
    asm volatile("ldmatrix.sync.aligned.m8n8.x4.shared.b16 {%0,%1,%2,%3}, [%4];" \
                 : "=r"(R[0]), "=r"(R[1]), "=r"(R[2]), "=r"(R[3]) : "r"(addr))

#define MMA16816(Dst, A, B0, B1) \
    asm volatile("mma.sync.aligned.m16n8k16.row.col.f32.bf16.bf16.f32 " \
                 "{%0,%1,%2,%3},{%4,%5,%6,%7},{%8,%9},{%0,%1,%2,%3};" \
                 : "+f"(Dst[0]), "+f"(Dst[1]), "+f"(Dst[2]), "+f"(Dst[3]) \
                 : "r"(A[0]), "r"(A[1]), "r"(A[2]), "r"(A[3]), "r"(B0), "r"(B1))

#define CP16(dst, src) \
    asm volatile("cp.async.cg.shared.global [%0], [%1], 16;" :: "r"(dst), "l"(src) : "memory")

__global__ void __launch_bounds__(256, 2) gemm_bf16x3() {
    __shared__ __align__(16) unsigned char smem[6 * 8192];   // 48 KB: A1,A2,A3,B1,B2,B3
    const int tid  = threadIdx.x;
    const int lane = tid & 31;
    const int warp = tid >> 5;
    const int warpM = (warp >> 1) * 32;   // 0,32,64,96
    const int warpN = (warp & 1) * 64;    // 0,64
    const int m0 = blockIdx.x * 128;
    const int n0 = blockIdx.y * 128;

    const uint32_t smem_u32 = (uint32_t)__cvta_generic_to_shared(smem);

    // ---- copy geometry: each thread owns (row, cu) and (row+64, cu) per tile
    const int crow = tid >> 2;                 // 0..63
    const int ccu  = tid & 3;                  // 16B unit within 64B row
    const uint32_t cswz = (uint32_t)((ccu ^ ((crow >> 1) & 3)) << 4);  // same for row and row+64
    const uint32_t cdst = smem_u32 + crow * 64 + cswz;
    const size_t csrcA = ((size_t)(m0 + crow)) * P_ + ccu * 8;   // element offsets
    const size_t csrcB = ((size_t)(n0 + crow)) * P_ + ccu * 8;

    // ---- ldmatrix address precompute
    const int rA  = lane & 15;
    const int cxA = lane >> 4;
    uint32_t offA[2][2];
#pragma unroll
    for (int mt = 0; mt < 2; mt++)
#pragma unroll
        for (int k16 = 0; k16 < 2; k16++) {
            int r = warpM + mt * 16 + rA;
            int c = k16 * 2 + cxA;
            offA[mt][k16] = smem_u32 + r * 64 + (uint32_t)((c ^ ((r >> 1) & 3)) << 4);
        }
    const int rBl = (lane & 7) + ((lane >> 4) & 1) * 8;
    const int cxB = (lane >> 3) & 1;
    uint32_t offB[4][2];
#pragma unroll
    for (int g = 0; g < 4; g++)
#pragma unroll
        for (int k16 = 0; k16 < 2; k16++) {
            int r = warpN + g * 16 + rBl;
            int c = k16 * 2 + cxB;
            offB[g][k16] = smem_u32 + 3 * 8192 + r * 64 + (uint32_t)((c ^ ((r >> 1) & 3)) << 4);
        }

    float acc[2][8][4];
#pragma unroll
    for (int i = 0; i < 2; i++)
#pragma unroll
        for (int j = 0; j < 8; j++)
#pragma unroll
            for (int k = 0; k < 4; k++) acc[i][j][k] = 0.f;

    // pairings (i,j) with i+j <= 2 (0-based): covers all terms >= 2^-27 rel
    const int PIA[6] = {0, 0, 1, 0, 2, 1};
    const int PJB[6] = {0, 1, 0, 2, 0, 1};

    for (int k0 = 0; k0 < P_; k0 += 32) {
        // ---- load 6 tiles (128x32 bf16 each) via cp.async
#pragma unroll
        for (int t = 0; t < 3; t++) {
            const char* sA = (const char*)(&g_SA[t][0]) + (csrcA + k0) * 2;
            uint32_t dA = cdst + t * 8192;
            CP16(dA, sA);
            CP16(dA + 4096, sA + (size_t)64 * P_ * 2);
            const char* sB = (const char*)(&g_SB[t][0]) + (csrcB + k0) * 2;
            uint32_t dB = dA + 3 * 8192;
            CP16(dB, sB);
            CP16(dB + 4096, sB + (size_t)64 * P_ * 2);
        }
        asm volatile("cp.async.commit_group;" ::: "memory");
        asm volatile("cp.async.wait_group 0;" ::: "memory");
        __syncthreads();

        // ---- 6 pairings x 2 k16-steps of HMMA
#pragma unroll
        for (int pr = 0; pr < 6; pr++) {
            const uint32_t Abase = (uint32_t)(PIA[pr] * 8192);
            const uint32_t Bbase = (uint32_t)(PJB[pr] * 8192);
#pragma unroll
            for (int k16 = 0; k16 < 2; k16++) {
                uint32_t a0[4], a1[4];
                LDSM4(a0, offA[0][k16] + Abase);
                LDSM4(a1, offA[1][k16] + Abase);
                uint32_t bf[4][4];
#pragma unroll
                for (int g = 0; g < 4; g++) LDSM4(bf[g], offB[g][k16] + Bbase);
#pragma unroll
                for (int g = 0; g < 4; g++) {
                    MMA16816(acc[0][2 * g],     a0, bf[g][0], bf[g][1]);
                    MMA16816(acc[0][2 * g + 1], a0, bf[g][2], bf[g][3]);
                    MMA16816(acc[1][2 * g],     a1, bf[g][0], bf[g][1]);
                    MMA16816(acc[1][2 * g + 1], a1, bf[g][2], bf[g][3]);
                }
            }
        }
        __syncthreads();
    }

    // ---- epilogue: fp32 accumulators -> g_H
    const int mrow = lane >> 2;
    const int ncol = (lane & 3) * 2;
#pragma unroll
    for (int mt = 0; mt < 2; mt++)
#pragma unroll
        for (int nt = 0; nt < 8; nt++) {
            int m = m0 + warpM + mt * 16 + mrow;
            int n = n0 + warpN + nt * 8 + ncol;
            *(float2*)&g_H[(size_t)m * D_ + n]       = make_float2(acc[mt][nt][0], acc[mt][nt][1]);
            *(float2*)&g_H[(size_t)(m + 8) * D_ + n] = make_float2(acc[mt][nt][2], acc[mt][nt][3]);
        }
}

// ---------------- BN stats: deterministic two-stage reduction --------------
__global__ void bn_partial_kernel() {
    int d = threadIdx.x;                 // 0..255
    int blk = blockIdx.x;                // 0..391
    const float* p = g_H + (size_t)blk * 128 * D_ + d;
    float s = 0.f, q = 0.f;
#pragma unroll 4
    for (int r = 0; r < 128; r++) {
        float v = p[(size_t)r * D_];
        s += v;
        q += v * v;
    }
    g_psum[blk * D_ + d] = s;
    g_psq [blk * D_ + d] = q;
}

__global__ void bn_final_kernel() {
    int d = blockIdx.x;                  // 0..255
    int tid = threadIdx.x;               // 0..127
    double s = 0.0, q = 0.0;
    for (int b = tid; b < NBLK_M; b += 128) {
        s += (double)g_psum[b * D_ + d];
        q += (double)g_psq [b * D_ + d];
    }
#pragma unroll
    for (int o = 16; o > 0; o >>= 1) {
        s += __shfl_down_sync(0xffffffffu, s, o);
        q += __shfl_down_sync(0xffffffffu, q, o);
    }
    __shared__ double sh[8];
    int w = tid >> 5;
    if ((tid & 31) == 0) { sh[w] = s; sh[4 + w] = q; }
    __syncthreads();
    if (tid == 0) {
        s = sh[0] + sh[1] + sh[2] + sh[3];
        q = sh[4] + sh[5] + sh[6] + sh[7];
        double m = s / (double)M_;
        double var = q / (double)M_ - m * m;
        g_mean[d]   = (float)m;
        g_invstd[d] = (float)(1.0 / sqrt(var + 1e-5));
    }
}

// ---------------- BN + LIF + PE + LIF fused over T -------------------------
__global__ void lif_kernel(const float* __restrict__ gamma,
                           const float* __restrict__ beta,
                           float* __restrict__ out) {
    int e = blockIdx.x * blockDim.x + threadIdx.x;
    if (e >= BND) return;
    int d = e & (D_ - 1);
    int bn = e >> 8;
    int n = bn % N_;

    float mu = g_mean[d];
    float is = g_invstd[d];
    float g  = gamma[d];
    float bt = beta[d];
    float p  = g_pe[n * D_ + d];

    float v1 = 0.f, v2 = 0.f;
#pragma unroll
    for (int t = 0; t < T_; t++) {
        float h = g_H[(size_t)t * BND + e];
        h = (h - mu) * is;
        h = h * g + bt;
        v1 = v1 + (h - v1) * 0.5f;
        float s1 = ((v1 - 0.5f) >= 0.f) ? 1.f : 0.f;
        v1 = v1 * (1.f - s1);
        float x2 = s1 + p;
        v2 = v2 + (x2 - v2) * 0.5f;
        float s2 = ((v2 - 0.5f) >= 0.f) ? 1.f : 0.f;
        v2 = v2 * (1.f - s2);
        out[(size_t)t * BND + e] = s2;
    }
}

// ---------------- launch ----------------------------------------------------
extern "C" void kernel_launch(void* const* d_in, const int* in_sizes, int n_in,
                              void* d_out, int out_size) {
    const float* x     = (const float*)d_in[0];   // [T,B,N,P]
    const float* W     = (const float*)d_in[1];   // [D,P]
    const float* gamma = (const float*)d_in[2];   // [D]
    const float* beta  = (const float*)d_in[3];   // [D]
    float* out = (float*)d_out;                   // [T,B,N,D]

    pe_kernel<<<N_, 128>>>();
    splitA_kernel<<<(int)(SA_ELEMS / 4 / 256), 256>>>(x);   // 37632 blocks
    splitB_kernel<<<(int)(SB_ELEMS / 4 / 256), 256>>>(W);   // 192 blocks
    gemm_bf16x3<<<dim3(NBLK_M, 2), 256>>>();
    bn_partial_kernel<<<NBLK_M, 256>>>();
    bn_final_kernel<<<D_, 128>>>();
    lif_kernel<<<BND / 256, 256>>>(gamma, beta, out);
}

// round 7
// speedup vs baseline: 1.5119x; 1.0937x over previous
#include <cuda_runtime.h>
#include <cuda_bf16.h>
#include <cstdint>
#include <math.h>

// Problem dims (fixed by the dataset)
#define T_  4
#define B_  64
#define N_  196
#define P_  768
#define D_  256
#define M_  (T_ * B_ * N_)        // 50176
#define BND (B_ * N_ * D_)        // 3211264
#define NBLK_M (M_ / 128)         // 392

static constexpr size_t SA_ELEMS = (size_t)M_ * P_;   // 38,535,168
static constexpr size_t SB_ELEMS = (size_t)D_ * P_;   // 196,608

// ---------------- scratch (allocation-free per harness rules) ----------------
__device__ float g_H[(size_t)M_ * D_];                 // GEMM output [M, D]
__device__ __nv_bfloat16 g_SA[3][SA_ELEMS];            // bf16x3 splits of x
__device__ __nv_bfloat16 g_SB[3][SB_ELEMS];            // bf16x3 splits of W
__device__ float g_psum[NBLK_M * D_];
__device__ float g_psq [NBLK_M * D_];
__device__ float g_mean[D_];
__device__ float g_invstd[D_];
__device__ float g_pe[N_ * D_];

// ---------------- tAPE positional encoding --------------------------------
__global__ void pe_kernel() {
    int n = blockIdx.x;          // 0..195
    int i = threadIdx.x;         // 0..127
    const float c = (float)(-9.210340371976184 / 256.0);
    float t = (float)(2 * i) * c;
    float div = (float)exp((double)t);
    float arg = ((float)n * div) * (float)(256.0 / 196.0);
    g_pe[n * D_ + 2 * i]     = (float)sin((double)arg);
    g_pe[n * D_ + 2 * i + 1] = (float)cos((double)arg);
}

// ---------------- fp32 -> bf16 x3 error-free split --------------------------
__device__ __forceinline__ unsigned pack2(unsigned short lo, unsigned short hi) {
    return (unsigned)lo | ((unsigned)hi << 16);
}

__device__ __forceinline__ void split4(const float4 v,
                                       __nv_bfloat16* p1, __nv_bfloat16* p2, __nv_bfloat16* p3) {
    float xs[4] = {v.x, v.y, v.z, v.w};
    unsigned short a1[4], a2[4], a3[4];
#pragma unroll
    for (int j = 0; j < 4; j++) {
        float x = xs[j];
        __nv_bfloat16 b1 = __float2bfloat16_rn(x);
        float r = x - __bfloat162float(b1);          // exact
        __nv_bfloat16 b2 = __float2bfloat16_rn(r);
        float r2 = r - __bfloat162float(b2);         // exact
        __nv_bfloat16 b3 = __float2bfloat16_rn(r2);
        a1[j] = *(unsigned short*)&b1;
        a2[j] = *(unsigned short*)&b2;
        a3[j] = *(unsigned short*)&b3;
    }
    uint2 u1 = {pack2(a1[0], a1[1]), pack2(a1[2], a1[3])};
    uint2 u2 = {pack2(a2[0], a2[1]), pack2(a2[2], a2[3])};
    uint2 u3 = {pack2(a3[0], a3[1]), pack2(a3[2], a3[3])};
    *(uint2*)p1 = u1;
    *(uint2*)p2 = u2;
    *(uint2*)p3 = u3;
}

__global__ void splitA_kernel(const float* __restrict__ x) {
    size_t i = ((size_t)blockIdx.x * 256 + threadIdx.x) * 4;
    float4 v = *(const float4*)(x + i);
    split4(v, &g_SA[0][i], &g_SA[1][i], &g_SA[2][i]);
}

__global__ void splitB_kernel(const float* __restrict__ w) {
    size_t i = ((size_t)blockIdx.x * 256 + threadIdx.x) * 4;
    float4 v = *(const float4*)(w + i);
    split4(v, &g_SB[0][i], &g_SB[1][i], &g_SB[2][i]);
}

// ---------------- bf16x3 tensor-core GEMM, double-buffered -------------------
// H[m,d] = sum_p x[m,p] * W[d,p], fp32 accuracy via 6 bf16 pairings.
#define LDSM4(R, addr) \
    asm volatile("ldmatrix.sync.aligned.m8n8.x4.shared.b16 {%0,%1,%2,%3}, [%4];" \
                 : "=r"(R[0]), "=r"(R[1]), "=r"(R[2]), "=r"(R[3]) : "r"(addr))

#define MMA16816(Dst, A, B0, B1) \
    asm volatile("mma.sync.aligned.m16n8k16.row.col.f32.bf16.bf16.f32 " \
                 "{%0,%1,%2,%3},{%4,%5,%6,%7},{%8,%9},{%0,%1,%2,%3};" \
                 : "+f"(Dst[0]), "+f"(Dst[1]), "+f"(Dst[2]), "+f"(Dst[3]) \
                 : "r"(A[0]), "r"(A[1]), "r"(A[2]), "r"(A[3]), "r"(B0), "r"(B1))

#define CP16(dst, src) \
    asm volatile("cp.async.cg.shared.global [%0], [%1], 16;" :: "r"(dst), "l"(src) : "memory")

// Stage layout: 6 tiles (A1,A2,A3,B1,B2,B3) of 128 rows x 16 cols bf16 = 4KB each.
// Row stride 32B (2 x 16B chunks). Swizzle: chunk cu stored at cu ^ ((row>>2)&1).
#define STAGE_BYTES 24576
#define TILE_BYTES  4096
#define KC 16
#define NSTAGES (P_ / KC)   // 48

__global__ void __launch_bounds__(256, 2) gemm_bf16x3() {
    __shared__ __align__(16) unsigned char smem[2 * STAGE_BYTES];   // 48 KB
    const int tid  = threadIdx.x;
    const int lane = tid & 31;
    const int warp = tid >> 5;
    const int warpM = (warp >> 1) * 32;   // 0,32,64,96
    const int warpN = (warp & 1) * 64;    // 0,64
    const int m0 = blockIdx.x * 128;
    const int n0 = blockIdx.y * 128;

    const uint32_t smem_u32 = (uint32_t)__cvta_generic_to_shared(smem);

    // ---- copy geometry: one 16B chunk per thread per tile
    const int crow = tid >> 1;                 // 0..127
    const int ccu  = tid & 1;                  // 16B unit within 32B row
    const uint32_t cdst0 = smem_u32 + (uint32_t)(crow * 32)
                         + (uint32_t)((ccu ^ ((crow >> 2) & 1)) << 4);
    const size_t csrcA = (size_t)(m0 + crow) * P_ + ccu * 8;   // element offset
    const size_t csrcB = (size_t)(n0 + crow) * P_ + ccu * 8;

    // ---- ldmatrix address precompute (within-stage offsets)
    // A fragment (m16 x k16): lanes 0-15 -> rows, lane>>4 -> k-chunk
    const int rAl = lane & 15;
    const int cxA = lane >> 4;
    uint32_t offA[2];
#pragma unroll
    for (int mt = 0; mt < 2; mt++) {
        int r = warpM + mt * 16 + rAl;
        offA[mt] = (uint32_t)(r * 32) + (uint32_t)(((cxA ^ ((r >> 2) & 1))) << 4);
    }
    // B fragment (n16 x k16 per ldmatrix.x4 group)
    const int rBl = (lane & 7) + ((lane >> 4) & 1) * 8;
    const int cxB = (lane >> 3) & 1;
    uint32_t offB[4];
#pragma unroll
    for (int g = 0; g < 4; g++) {
        int r = warpN + g * 16 + rBl;
        offB[g] = (uint32_t)(3 * TILE_BYTES) + (uint32_t)(r * 32)
                + (uint32_t)(((cxB ^ ((r >> 2) & 1))) << 4);
    }

    float acc[2][8][4];
#pragma unroll
    for (int i = 0; i < 2; i++)
#pragma unroll
        for (int j = 0; j < 8; j++)
#pragma unroll
            for (int k = 0; k < 4; k++) acc[i][j][k] = 0.f;

    // ---- stage loader
    auto load_stage = [&](int ks, int stage) {
        const uint32_t so = cdst0 + (uint32_t)(stage * STAGE_BYTES);
        const size_t kof = (size_t)ks * KC;
#pragma unroll
        for (int t = 0; t < 3; t++) {
            CP16(so + t * TILE_BYTES,
                 (const char*)(&g_SA[t][0]) + (csrcA + kof) * 2);
            CP16(so + (t + 3) * TILE_BYTES,
                 (const char*)(&g_SB[t][0]) + (csrcB + kof) * 2);
        }
        asm volatile("cp.async.commit_group;" ::: "memory");
    };

    // ---- stage compute: pairings grouped by B split to reuse B fragments
    auto compute_stage = [&](int stage) {
        const uint32_t so = smem_u32 + (uint32_t)(stage * STAGE_BYTES);
#pragma unroll
        for (int j = 0; j < 3; j++) {
            const uint32_t Bb = so + (uint32_t)(j * TILE_BYTES);
            uint32_t bf[4][4];
#pragma unroll
            for (int g = 0; g < 4; g++) LDSM4(bf[g], offB[g] + Bb);
#pragma unroll
            for (int i = 0; i < 3 - j; i++) {          // i + j <= 2
                const uint32_t Ab = so + (uint32_t)(i * TILE_BYTES);
                uint32_t a0[4], a1[4];
                LDSM4(a0, offA[0] + Ab);
                LDSM4(a1, offA[1] + Ab);
#pragma unroll
                for (int g = 0; g < 4; g++) {
                    MMA16816(acc[0][2 * g],     a0, bf[g][0], bf[g][1]);
                    MMA16816(acc[0][2 * g + 1], a0, bf[g][2], bf[g][3]);
                    MMA16816(acc[1][2 * g],     a1, bf[g][0], bf[g][1]);
                    MMA16816(acc[1][2 * g + 1], a1, bf[g][2], bf[g][3]);
                }
            }
        }
    };

    // ---- double-buffered mainloop
    load_stage(0, 0);
    for (int it = 0; it < NSTAGES; it++) {
        if (it + 1 < NSTAGES) {
            load_stage(it + 1, (it + 1) & 1);
            asm volatile("cp.async.wait_group 1;" ::: "memory");
        } else {
            asm volatile("cp.async.wait_group 0;" ::: "memory");
        }
        __syncthreads();
        compute_stage(it & 1);
        __syncthreads();   // protect buffer (it&1) before it is reloaded at it+2
    }

    // ---- epilogue: fp32 accumulators -> g_H
    const int mrow = lane >> 2;
    const int ncol = (lane & 3) * 2;
#pragma unroll
    for (int mt = 0; mt < 2; mt++)
#pragma unroll
        for (int nt = 0; nt < 8; nt++) {
            int m = m0 + warpM + mt * 16 + mrow;
            int n = n0 + warpN + nt * 8 + ncol;
            *(float2*)&g_H[(size_t)m * D_ + n]       = make_float2(acc[mt][nt][0], acc[mt][nt][1]);
            *(float2*)&g_H[(size_t)(m + 8) * D_ + n] = make_float2(acc[mt][nt][2], acc[mt][nt][3]);
        }
}

// ---------------- BN stats: deterministic two-stage reduction --------------
__global__ void bn_partial_kernel() {
    int d = threadIdx.x;                 // 0..255
    int blk = blockIdx.x;                // 0..391
    const float* p = g_H + (size_t)blk * 128 * D_ + d;
    float s = 0.f, q = 0.f;
#pragma unroll 4
    for (int r = 0; r < 128; r++) {
        float v = p[(size_t)r * D_];
        s += v;
        q += v * v;
    }
    g_psum[blk * D_ + d] = s;
    g_psq [blk * D_ + d] = q;
}

__global__ void bn_final_kernel() {
    int d = blockIdx.x;                  // 0..255
    int tid = threadIdx.x;               // 0..127
    double s = 0.0, q = 0.0;
    for (int b = tid; b < NBLK_M; b += 128) {
        s += (double)g_psum[b * D_ + d];
        q += (double)g_psq [b * D_ + d];
    }
#pragma unroll
    for (int o = 16; o > 0; o >>= 1) {
        s += __shfl_down_sync(0xffffffffu, s, o);
        q += __shfl_down_sync(0xffffffffu, q, o);
    }
    __shared__ double sh[8];
    int w = tid >> 5;
    if ((tid & 31) == 0) { sh[w] = s; sh[4 + w] = q; }
    __syncthreads();
    if (tid == 0) {
        s = sh[0] + sh[1] + sh[2] + sh[3];
        q = sh[4] + sh[5] + sh[6] + sh[7];
        double m = s / (double)M_;
        double var = q / (double)M_ - m * m;
        g_mean[d]   = (float)m;
        g_invstd[d] = (float)(1.0 / sqrt(var + 1e-5));
    }
}

// ---------------- BN + LIF + PE + LIF fused over T -------------------------
__global__ void lif_kernel(const float* __restrict__ gamma,
                           const float* __restrict__ beta,
                           float* __restrict__ out) {
    int e = blockIdx.x * blockDim.x + threadIdx.x;
    if (e >= BND) return;
    int d = e & (D_ - 1);
    int bn = e >> 8;
    int n = bn % N_;

    float mu = g_mean[d];
    float is = g_invstd[d];
    float g  = gamma[d];
    float bt = beta[d];
    float p  = g_pe[n * D_ + d];

    float v1 = 0.f, v2 = 0.f;
#pragma unroll
    for (int t = 0; t < T_; t++) {
        float h = g_H[(size_t)t * BND + e];
        h = (h - mu) * is;
        h = h * g + bt;
        v1 = v1 + (h - v1) * 0.5f;
        float s1 = ((v1 - 0.5f) >= 0.f) ? 1.f : 0.f;
        v1 = v1 * (1.f - s1);
        float x2 = s1 + p;
        v2 = v2 + (x2 - v2) * 0.5f;
        float s2 = ((v2 - 0.5f) >= 0.f) ? 1.f : 0.f;
        v2 = v2 * (1.f - s2);
        out[(size_t)t * BND + e] = s2;
    }
}

// ---------------- launch ----------------------------------------------------
extern "C" void kernel_launch(void* const* d_in, const int* in_sizes, int n_in,
                              void* d_out, int out_size) {
    const float* x     = (const float*)d_in[0];   // [T,B,N,P]
    const float* W     = (const float*)d_in[1];   // [D,P]
    const float* gamma = (const float*)d_in[2];   // [D]
    const float* beta  = (const float*)d_in[3];   // [D]
    float* out = (float*)d_out;                   // [T,B,N,D]

    pe_kernel<<<N_, 128>>>();
    splitA_kernel<<<(int)(SA_ELEMS / 4 / 256), 256>>>(x);   // 37632 blocks
    splitB_kernel<<<(int)(SB_ELEMS / 4 / 256), 256>>>(W);   // 192 blocks
    gemm_bf16x3<<<dim3(NBLK_M, 2), 256>>>();
    bn_partial_kernel<<<NBLK_M, 256>>>();
    bn_final_kernel<<<D_, 128>>>();
    lif_kernel<<<BND / 256, 256>>>(gamma, beta, out);
}

// round 10
// speedup vs baseline: 1.5835x; 1.0473x over previous
#include <cuda_runtime.h>
#include <cuda_bf16.h>
#include <cstdint>
#include <math.h>

// Problem dims (fixed by the dataset)
#define T_  4
#define B_  64
#define N_  196
#define P_  768
#define D_  256
#define M_  (T_ * B_ * N_)        // 50176
#define BND (B_ * N_ * D_)        // 3211264
#define NBLK_M (M_ / 128)         // 392

static constexpr size_t SA_ELEMS = (size_t)M_ * P_;   // 38,535,168
static constexpr size_t SB_ELEMS = (size_t)D_ * P_;   // 196,608

// ---------------- scratch (allocation-free per harness rules) ----------------
__device__ float g_H[(size_t)M_ * D_];                 // GEMM output [M, D]
__device__ __nv_bfloat16 g_SA[3][SA_ELEMS];            // bf16x3 splits of x
__device__ __nv_bfloat16 g_SB[3][SB_ELEMS];            // bf16x3 splits of W
__device__ float g_psum[NBLK_M * D_];
__device__ float g_psq [NBLK_M * D_];
__device__ float g_mean[D_];
__device__ float g_invstd[D_];
__device__ float g_pe[N_ * D_];

// ---------------- tAPE positional encoding --------------------------------
__global__ void pe_kernel() {
    int n = blockIdx.x;          // 0..195
    int i = threadIdx.x;         // 0..127
    const float c = (float)(-9.210340371976184 / 256.0);
    float t = (float)(2 * i) * c;
    float div = (float)exp((double)t);
    float arg = ((float)n * div) * (float)(256.0 / 196.0);
    g_pe[n * D_ + 2 * i]     = (float)sin((double)arg);
    g_pe[n * D_ + 2 * i + 1] = (float)cos((double)arg);
}

// ---------------- fp32 -> bf16 x3 error-free split --------------------------
__device__ __forceinline__ unsigned pack2(unsigned short lo, unsigned short hi) {
    return (unsigned)lo | ((unsigned)hi << 16);
}

__device__ __forceinline__ void split4(const float4 v,
                                       __nv_bfloat16* p1, __nv_bfloat16* p2, __nv_bfloat16* p3) {
    float xs[4] = {v.x, v.y, v.z, v.w};
    unsigned short a1[4], a2[4], a3[4];
#pragma unroll
    for (int j = 0; j < 4; j++) {
        float x = xs[j];
        __nv_bfloat16 b1 = __float2bfloat16_rn(x);
        float r = x - __bfloat162float(b1);          // exact
        __nv_bfloat16 b2 = __float2bfloat16_rn(r);
        float r2 = r - __bfloat162float(b2);         // exact
        __nv_bfloat16 b3 = __float2bfloat16_rn(r2);
        a1[j] = *(unsigned short*)&b1;
        a2[j] = *(unsigned short*)&b2;
        a3[j] = *(unsigned short*)&b3;
    }
    uint2 u1 = {pack2(a1[0], a1[1]), pack2(a1[2], a1[3])};
    uint2 u2 = {pack2(a2[0], a2[1]), pack2(a2[2], a2[3])};
    uint2 u3 = {pack2(a3[0], a3[1]), pack2(a3[2], a3[3])};
    *(uint2*)p1 = u1;
    *(uint2*)p2 = u2;
    *(uint2*)p3 = u3;
}

__global__ void splitA_kernel(const float* __restrict__ x) {
    size_t i = ((size_t)blockIdx.x * 256 + threadIdx.x) * 4;
    float4 v = *(const float4*)(x + i);
    split4(v, &g_SA[0][i], &g_SA[1][i], &g_SA[2][i]);
}

__global__ void splitB_kernel(const float* __restrict__ w) {
    size_t i = ((size_t)blockIdx.x * 256 + threadIdx.x) * 4;
    float4 v = *(const float4*)(w + i);
    split4(v, &g_SB[0][i], &g_SB[1][i], &g_SB[2][i]);
}

// ---------------- bf16x3 tensor-core GEMM, 3-stage pipeline -----------------
// H[m,d] = sum_p x[m,p] * W[d,p], fp32 accuracy via 6 bf16 pairings.
// Arithmetic order identical to the 2-stage version (bitwise-same results).
#define LDSM4(R, addr) \
    asm volatile("ldmatrix.sync.aligned.m8n8.x4.shared.b16 {%0,%1,%2,%3}, [%4];" \
                 : "=r"(R[0]), "=r"(R[1]), "=r"(R[2]), "=r"(R[3]) : "r"(addr))

#define MMA16816(Dst, A, B0, B1) \
    asm volatile("mma.sync.aligned.m16n8k16.row.col.f32.bf16.bf16.f32 " \
                 "{%0,%1,%2,%3},{%4,%5,%6,%7},{%8,%9},{%0,%1,%2,%3};" \
                 : "+f"(Dst[0]), "+f"(Dst[1]), "+f"(Dst[2]), "+f"(Dst[3]) \
                 : "r"(A[0]), "r"(A[1]), "r"(A[2]), "r"(A[3]), "r"(B0), "r"(B1))

#define CP16(dst, src) \
    asm volatile("cp.async.cg.shared.global [%0], [%1], 16;" :: "r"(dst), "l"(src) : "memory")

// Stage layout: 6 tiles (A1,A2,A3,B1,B2,B3) of 128 rows x 16 cols bf16 = 4KB each.
// Row stride 32B (2 x 16B chunks). Swizzle: chunk cu stored at cu ^ ((row>>2)&1).
#define STAGE_BYTES 24576
#define TILE_BYTES  4096
#define KC 16
#define NST (P_ / KC)        // 48
#define NPIPE 3
#define SMEM_DYN (NPIPE * STAGE_BYTES)   // 73728

__global__ void __launch_bounds__(256, 2) gemm_bf16x3() {
    extern __shared__ __align__(16) unsigned char smem[];
    const int tid  = threadIdx.x;
    const int lane = tid & 31;
    const int warp = tid >> 5;
    const int warpM = (warp >> 1) * 32;   // 0,32,64,96
    const int warpN = (warp & 1) * 64;    // 0,64
    const int n0 = blockIdx.x * 128;      // n fastest: N-tile pair shares A via L2
    const int m0 = blockIdx.y * 128;

    const uint32_t smem_u32 = (uint32_t)__cvta_generic_to_shared(smem);

    // ---- copy geometry: one 16B chunk per thread per tile
    const int crow = tid >> 1;                 // 0..127
    const int ccu  = tid & 1;                  // 16B unit within 32B row
    const uint32_t cdst0 = smem_u32 + (uint32_t)(crow * 32)
                         + (uint32_t)((ccu ^ ((crow >> 2) & 1)) << 4);
    const size_t csrcA = (size_t)(m0 + crow) * P_ + ccu * 8;   // element offset
    const size_t csrcB = (size_t)(n0 + crow) * P_ + ccu * 8;

    // ---- ldmatrix address precompute (within-stage offsets)
    const int rAl = lane & 15;
    const int cxA = lane >> 4;
    uint32_t offA[2];
#pragma unroll
    for (int mt = 0; mt < 2; mt++) {
        int r = warpM + mt * 16 + rAl;
        offA[mt] = (uint32_t)(r * 32) + (uint32_t)(((cxA ^ ((r >> 2) & 1))) << 4);
    }
    const int rBl = (lane & 7) + ((lane >> 4) & 1) * 8;
    const int cxB = (lane >> 3) & 1;
    uint32_t offB[4];
#pragma unroll
    for (int g = 0; g < 4; g++) {
        int r = warpN + g * 16 + rBl;
        offB[g] = (uint32_t)(3 * TILE_BYTES) + (uint32_t)(r * 32)
                + (uint32_t)(((cxB ^ ((r >> 2) & 1))) << 4);
    }

    float acc[2][8][4];
#pragma unroll
    for (int i = 0; i < 2; i++)
#pragma unroll
        for (int j = 0; j < 8; j++)
#pragma unroll
            for (int k = 0; k < 4; k++) acc[i][j][k] = 0.f;

    // ---- stage loader
    auto load_stage = [&](int ks, int stage) {
        const uint32_t so = cdst0 + (uint32_t)(stage * STAGE_BYTES);
        const size_t kof = (size_t)ks * KC;
#pragma unroll
        for (int t = 0; t < 3; t++) {
            CP16(so + t * TILE_BYTES,
                 (const char*)(&g_SA[t][0]) + (csrcA + kof) * 2);
            CP16(so + (t + 3) * TILE_BYTES,
                 (const char*)(&g_SB[t][0]) + (csrcB + kof) * 2);
        }
        asm volatile("cp.async.commit_group;" ::: "memory");
    };

    // ---- stage compute: pairings grouped by B split (same order as before)
    auto compute_stage = [&](int stage) {
        const uint32_t so = smem_u32 + (uint32_t)(stage * STAGE_BYTES);
#pragma unroll
        for (int j = 0; j < 3; j++) {
            const uint32_t Bb = so + (uint32_t)(j * TILE_BYTES);
            uint32_t bf[4][4];
#pragma unroll
            for (int g = 0; g < 4; g++) LDSM4(bf[g], offB[g] + Bb);
#pragma unroll
            for (int i = 0; i < 3 - j; i++) {          // i + j <= 2
                const uint32_t Ab = so + (uint32_t)(i * TILE_BYTES);
                uint32_t a0[4], a1[4];
                LDSM4(a0, offA[0] + Ab);
                LDSM4(a1, offA[1] + Ab);
#pragma unroll
                for (int g = 0; g < 4; g++) {
                    MMA16816(acc[0][2 * g],     a0, bf[g][0], bf[g][1]);
                    MMA16816(acc[0][2 * g + 1], a0, bf[g][2], bf[g][3]);
                    MMA16816(acc[1][2 * g],     a1, bf[g][0], bf[g][1]);
                    MMA16816(acc[1][2 * g + 1], a1, bf[g][2], bf[g][3]);
                }
            }
        }
    };

    // ---- 3-stage ring mainloop: one barrier per iteration
    load_stage(0, 0);
    load_stage(1, 1);
    for (int it = 0; it < NST; it++) {
        const int s = it % NPIPE;
        if (it < NST - 2) {
            asm volatile("cp.async.wait_group 1;" ::: "memory");   // load it done
        } else {
            asm volatile("cp.async.wait_group 0;" ::: "memory");
        }
        __syncthreads();   // all warps: load it visible; compute it-1 drained
        if (it + 2 < NST) load_stage(it + 2, (it + 2) % NPIPE);
        compute_stage(s);
    }

    // ---- epilogue: fp32 accumulators -> g_H
    const int mrow = lane >> 2;
    const int ncol = (lane & 3) * 2;
#pragma unroll
    for (int mt = 0; mt < 2; mt++)
#pragma unroll
        for (int nt = 0; nt < 8; nt++) {
            int m = m0 + warpM + mt * 16 + mrow;
            int n = n0 + warpN + nt * 8 + ncol;
            *(float2*)&g_H[(size_t)m * D_ + n]       = make_float2(acc[mt][nt][0], acc[mt][nt][1]);
            *(float2*)&g_H[(size_t)(m + 8) * D_ + n] = make_float2(acc[mt][nt][2], acc[mt][nt][3]);
        }
}

// ---------------- BN stats: deterministic two-stage reduction --------------
__global__ void bn_partial_kernel() {
    int d = threadIdx.x;                 // 0..255
    int blk = blockIdx.x;                // 0..391
    const float* p = g_H + (size_t)blk * 128 * D_ + d;
    float s = 0.f, q = 0.f;
#pragma unroll 4
    for (int r = 0; r < 128; r++) {
        float v = p[(size_t)r * D_];
        s += v;
        q += v * v;
    }
    g_psum[blk * D_ + d] = s;
    g_psq [blk * D_ + d] = q;
}

__global__ void bn_final_kernel() {
    int d = blockIdx.x;                  // 0..255
    int tid = threadIdx.x;               // 0..127
    double s = 0.0, q = 0.0;
    for (int b = tid; b < NBLK_M; b += 128) {
        s += (double)g_psum[b * D_ + d];
        q += (double)g_psq [b * D_ + d];
    }
#pragma unroll
    for (int o = 16; o > 0; o >>= 1) {
        s += __shfl_down_sync(0xffffffffu, s, o);
        q += __shfl_down_sync(0xffffffffu, q, o);
    }
    __shared__ double sh[8];
    int w = tid >> 5;
    if ((tid & 31) == 0) { sh[w] = s; sh[4 + w] = q; }
    __syncthreads();
    if (tid == 0) {
        s = sh[0] + sh[1] + sh[2] + sh[3];
        q = sh[4] + sh[5] + sh[6] + sh[7];
        double m = s / (double)M_;
        double var = q / (double)M_ - m * m;
        g_mean[d]   = (float)m;
        g_invstd[d] = (float)(1.0 / sqrt(var + 1e-5));
    }
}

// ---------------- BN + LIF + PE + LIF fused over T -------------------------
__global__ void lif_kernel(const float* __restrict__ gamma,
                           const float* __restrict__ beta,
                           float* __restrict__ out) {
    int e = blockIdx.x * blockDim.x + threadIdx.x;
    if (e >= BND) return;
    int d = e & (D_ - 1);
    int bn = e >> 8;
    int n = bn % N_;

    float mu = g_mean[d];
    float is = g_invstd[d];
    float g  = gamma[d];
    float bt = beta[d];
    float p  = g_pe[n * D_ + d];

    float v1 = 0.f, v2 = 0.f;
#pragma unroll
    for (int t = 0; t < T_; t++) {
        float h = g_H[(size_t)t * BND + e];
        h = (h - mu) * is;
        h = h * g + bt;
        v1 = v1 + (h - v1) * 0.5f;
        float s1 = ((v1 - 0.5f) >= 0.f) ? 1.f : 0.f;
        v1 = v1 * (1.f - s1);
        float x2 = s1 + p;
        v2 = v2 + (x2 - v2) * 0.5f;
        float s2 = ((v2 - 0.5f) >= 0.f) ? 1.f : 0.f;
        v2 = v2 * (1.f - s2);
        out[(size_t)t * BND + e] = s2;
    }
}

// ---------------- launch ----------------------------------------------------
extern "C" void kernel_launch(void* const* d_in, const int* in_sizes, int n_in,
                              void* d_out, int out_size) {
    const float* x     = (const float*)d_in[0];   // [T,B,N,P]
    const float* W     = (const float*)d_in[1];   // [D,P]
    const float* gamma = (const float*)d_in[2];   // [D]
    const float* beta  = (const float*)d_in[3];   // [D]
    float* out = (float*)d_out;                   // [T,B,N,D]

    cudaFuncSetAttribute(gemm_bf16x3,
                         cudaFuncAttributeMaxDynamicSharedMemorySize, SMEM_DYN);

    pe_kernel<<<N_, 128>>>();
    splitA_kernel<<<(int)(SA_ELEMS / 4 / 256), 256>>>(x);   // 37632 blocks
    splitB_kernel<<<(int)(SB_ELEMS / 4 / 256), 256>>>(W);   // 192 blocks
    gemm_bf16x3<<<dim3(2, NBLK_M), 256, SMEM_DYN>>>();
    bn_partial_kernel<<<NBLK_M, 256>>>();
    bn_final_kernel<<<D_, 128>>>();
    lif_kernel<<<BND / 256, 256>>>(gamma, beta, out);
}

// round 11
// speedup vs baseline: 1.7921x; 1.1317x over previous
#include <cuda_runtime.h>
#include <cuda_bf16.h>
#include <cstdint>
#include <math.h>

// Problem dims (fixed by the dataset)
#define T_  4
#define B_  64
#define N_  196
#define P_  768
#define D_  256
#define M_  (T_ * B_ * N_)        // 50176
#define BND (B_ * N_ * D_)        // 3211264
#define NBLK_M (M_ / 128)         // 392

static constexpr size_t SB_ELEMS = (size_t)D_ * P_;   // 196,608

// ---------------- scratch (allocation-free per harness rules) ----------------
__device__ float g_H[(size_t)M_ * D_];                 // GEMM output [M, D]
__device__ __nv_bfloat16 g_SB[3][SB_ELEMS];            // bf16x3 splits of W
__device__ float g_psum[NBLK_M * D_];
__device__ float g_psq [NBLK_M * D_];
__device__ float g_mean[D_];
__device__ float g_invstd[D_];
__device__ float g_pe[N_ * D_];

// ---------------- tAPE positional encoding --------------------------------
__global__ void pe_kernel() {
    int n = blockIdx.x;          // 0..195
    int i = threadIdx.x;         // 0..127
    const float c = (float)(-9.210340371976184 / 256.0);
    float t = (float)(2 * i) * c;
    float div = (float)exp((double)t);
    float arg = ((float)n * div) * (float)(256.0 / 196.0);
    g_pe[n * D_ + 2 * i]     = (float)sin((double)arg);
    g_pe[n * D_ + 2 * i + 1] = (float)cos((double)arg);
}

// ---------------- fp32 -> bf16 x3 error-free split --------------------------
__device__ __forceinline__ unsigned pack2(unsigned short lo, unsigned short hi) {
    return (unsigned)lo | ((unsigned)hi << 16);
}

__device__ __forceinline__ void split1(float x, unsigned short& o1,
                                       unsigned short& o2, unsigned short& o3) {
    __nv_bfloat16 b1 = __float2bfloat16_rn(x);
    float r = x - __bfloat162float(b1);          // exact
    __nv_bfloat16 b2 = __float2bfloat16_rn(r);
    float r2 = r - __bfloat162float(b2);         // exact
    __nv_bfloat16 b3 = __float2bfloat16_rn(r2);
    o1 = *(unsigned short*)&b1;
    o2 = *(unsigned short*)&b2;
    o3 = *(unsigned short*)&b3;
}

__device__ __forceinline__ void split4(const float4 v,
                                       __nv_bfloat16* p1, __nv_bfloat16* p2, __nv_bfloat16* p3) {
    float xs[4] = {v.x, v.y, v.z, v.w};
    unsigned short a1[4], a2[4], a3[4];
#pragma unroll
    for (int j = 0; j < 4; j++) split1(xs[j], a1[j], a2[j], a3[j]);
    uint2 u1 = {pack2(a1[0], a1[1]), pack2(a1[2], a1[3])};
    uint2 u2 = {pack2(a2[0], a2[1]), pack2(a2[2], a2[3])};
    uint2 u3 = {pack2(a3[0], a3[1]), pack2(a3[2], a3[3])};
    *(uint2*)p1 = u1;
    *(uint2*)p2 = u2;
    *(uint2*)p3 = u3;
}

__global__ void splitB_kernel(const float* __restrict__ w) {
    size_t i = ((size_t)blockIdx.x * 256 + threadIdx.x) * 4;
    float4 v = *(const float4*)(w + i);
    split4(v, &g_SB[0][i], &g_SB[1][i], &g_SB[2][i]);
}

// ---------------- bf16x3 tensor-core GEMM, fused A-split --------------------
// H[m,d] = sum_p x[m,p] * W[d,p], fp32 accuracy via 6 bf16 pairings.
// A split computed in-kernel (bitwise-identical to the old splitA kernel).
#define LDSM4(R, addr) \
    asm volatile("ldmatrix.sync.aligned.m8n8.x4.shared.b16 {%0,%1,%2,%3}, [%4];" \
                 : "=r"(R[0]), "=r"(R[1]), "=r"(R[2]), "=r"(R[3]) : "r"(addr))

#define MMA16816(Dst, A, B0, B1) \
    asm volatile("mma.sync.aligned.m16n8k16.row.col.f32.bf16.bf16.f32 " \
                 "{%0,%1,%2,%3},{%4,%5,%6,%7},{%8,%9},{%0,%1,%2,%3};" \
                 : "+f"(Dst[0]), "+f"(Dst[1]), "+f"(Dst[2]), "+f"(Dst[3]) \
                 : "r"(A[0]), "r"(A[1]), "r"(A[2]), "r"(A[3]), "r"(B0), "r"(B1))

#define CP16(dst, src) \
    asm volatile("cp.async.cg.shared.global [%0], [%1], 16;" :: "r"(dst), "l"(src) : "memory")

// Tiles: 128 rows x 16 cols bf16 = 4KB, row stride 32B (2 x 16B chunks),
// chunk cu stored at cu ^ ((row>>2)&1)  (unchanged layout -> same ldmatrix).
#define TILE_BYTES  4096
#define ABUF_BYTES  (3 * TILE_BYTES)     // one A stage: levels A1,A2,A3
#define BBUF_BYTES  (3 * TILE_BYTES)     // one B stage: levels B1,B2,B3
#define KC 16
#define NST (P_ / KC)        // 48
#define B_OFF (2 * ABUF_BYTES)           // A double-buffered, then B x3
#define SMEM_DYN (2 * ABUF_BYTES + 3 * BBUF_BYTES)   // 61440

__global__ void __launch_bounds__(256, 2) gemm_bf16x3(const float* __restrict__ x) {
    extern __shared__ __align__(16) unsigned char smem[];
    const int tid  = threadIdx.x;
    const int lane = tid & 31;
    const int warp = tid >> 5;
    const int warpM = (warp >> 1) * 32;   // 0,32,64,96
    const int warpN = (warp & 1) * 64;    // 0,64
    const int n0 = blockIdx.x * 128;      // n fastest: N-tile pair shares A via L2
    const int m0 = blockIdx.y * 128;

    const uint32_t smem_u32 = (uint32_t)__cvta_generic_to_shared(smem);

    // ---- per-thread A geometry: row = tid>>1, 8-float half h = tid&1
    const int arow = tid >> 1;
    const int ah   = tid & 1;
    const uint32_t asts = (uint32_t)(arow * 32) + (uint32_t)((ah ^ ((arow >> 2) & 1)) << 4);
    const float* axp = x + (size_t)(m0 + arow) * P_ + ah * 8;

    // ---- per-thread B cp.async geometry: one 16B chunk per tile
    const int crow = tid >> 1;
    const int ccu  = tid & 1;
    const uint32_t cdst0 = (uint32_t)(crow * 32) + (uint32_t)((ccu ^ ((crow >> 2) & 1)) << 4);
    const size_t csrcB = (size_t)(n0 + crow) * P_ + ccu * 8;

    // ---- ldmatrix address precompute (within-tile offsets)
    const int rAl = lane & 15;
    const int cxA = lane >> 4;
    uint32_t offA[2];
#pragma unroll
    for (int mt = 0; mt < 2; mt++) {
        int r = warpM + mt * 16 + rAl;
        offA[mt] = (uint32_t)(r * 32) + (uint32_t)(((cxA ^ ((r >> 2) & 1))) << 4);
    }
    const int rBl = (lane & 7) + ((lane >> 4) & 1) * 8;
    const int cxB = (lane >> 3) & 1;
    uint32_t offB[4];
#pragma unroll
    for (int g = 0; g < 4; g++) {
        int r = warpN + g * 16 + rBl;
        offB[g] = (uint32_t)(r * 32) + (uint32_t)(((cxB ^ ((r >> 2) & 1))) << 4);
    }

    float acc[2][8][4];
#pragma unroll
    for (int i = 0; i < 2; i++)
#pragma unroll
        for (int j = 0; j < 8; j++)
#pragma unroll
            for (int k = 0; k < 4; k++) acc[i][j][k] = 0.f;

    // ---- A helpers: LDG 8 floats; split + STS into 3 level tiles
    float4 ra0, ra1;
    auto ldgA = [&](int ks) {
        const float* p = axp + ks * KC;
        ra0 = *(const float4*)p;
        ra1 = *(const float4*)(p + 4);
    };
    auto stsA = [&](int abuf) {
        float xs[8] = {ra0.x, ra0.y, ra0.z, ra0.w, ra1.x, ra1.y, ra1.z, ra1.w};
        unsigned short l1[8], l2[8], l3[8];
#pragma unroll
        for (int j = 0; j < 8; j++) split1(xs[j], l1[j], l2[j], l3[j]);
        unsigned char* base = smem + abuf * ABUF_BYTES + asts;
        *(uint4*)(base)                 = make_uint4(pack2(l1[0], l1[1]), pack2(l1[2], l1[3]),
                                                    pack2(l1[4], l1[5]), pack2(l1[6], l1[7]));
        *(uint4*)(base + TILE_BYTES)    = make_uint4(pack2(l2[0], l2[1]), pack2(l2[2], l2[3]),
                                                    pack2(l2[4], l2[5]), pack2(l2[6], l2[7]));
        *(uint4*)(base + 2 * TILE_BYTES)= make_uint4(pack2(l3[0], l3[1]), pack2(l3[2], l3[3]),
                                                    pack2(l3[4], l3[5]), pack2(l3[6], l3[7]));
    };

    // ---- B stage loader (cp.async, 3 levels, one commit group)
    auto loadB = [&](int ks, int bbuf) {
        const uint32_t so = smem_u32 + (uint32_t)(B_OFF + bbuf * BBUF_BYTES) + cdst0;
        const size_t kof = (size_t)ks * KC;
#pragma unroll
        for (int t = 0; t < 3; t++)
            CP16(so + t * TILE_BYTES,
                 (const char*)(&g_SB[t][0]) + (csrcB + kof) * 2);
        asm volatile("cp.async.commit_group;" ::: "memory");
    };

    // ---- stage compute: identical op order to previous rounds
    auto compute_stage = [&](uint32_t aBase, uint32_t bBase) {
#pragma unroll
        for (int j = 0; j < 3; j++) {
            const uint32_t Bb = bBase + (uint32_t)(j * TILE_BYTES);
            uint32_t bf[4][4];
#pragma unroll
            for (int g = 0; g < 4; g++) LDSM4(bf[g], offB[g] + Bb);
#pragma unroll
            for (int i = 0; i < 3 - j; i++) {          // i + j <= 2
                const uint32_t Ab = aBase + (uint32_t)(i * TILE_BYTES);
                uint32_t a0[4], a1[4];
                LDSM4(a0, offA[0] + Ab);
                LDSM4(a1, offA[1] + Ab);
#pragma unroll
                for (int g = 0; g < 4; g++) {
                    MMA16816(acc[0][2 * g],     a0, bf[g][0], bf[g][1]);
                    MMA16816(acc[0][2 * g + 1], a0, bf[g][2], bf[g][3]);
                    MMA16816(acc[1][2 * g],     a1, bf[g][0], bf[g][1]);
                    MMA16816(acc[1][2 * g + 1], a1, bf[g][2], bf[g][3]);
                }
            }
        }
    };

    // ---- prologue
    loadB(0, 0);
    loadB(1, 1);
    ldgA(0);
    stsA(0);            // A stage 0 -> buffer 0 (published by first sync)
    ldgA(1);

    // ---- mainloop: one barrier per iteration
    for (int it = 0; it < NST; it++) {
        if (it < NST - 1) {
            asm volatile("cp.async.wait_group 1;" ::: "memory");   // B(it) done
        } else {
            asm volatile("cp.async.wait_group 0;" ::: "memory");
        }
        __syncthreads();   // publish B(it) + A-STS(it) ; compute(it-1) drained
        if (it + 1 < NST) stsA((it + 1) & 1);     // buffer (it+1)&1 == (it-1)&1, drained
        if (it + 2 < NST) {
            ldgA(it + 2);
            loadB(it + 2, (it + 2) % 3);          // buffer (it+2)%3 == (it-1)%3, drained
        }
        compute_stage(smem_u32 + (uint32_t)((it & 1) * ABUF_BYTES),
                      smem_u32 + (uint32_t)(B_OFF + (it % 3) * BBUF_BYTES));
    }

    // ---- epilogue: fp32 accumulators -> g_H
    const int mrow = lane >> 2;
    const int ncol = (lane & 3) * 2;
#pragma unroll
    for (int mt = 0; mt < 2; mt++)
#pragma unroll
        for (int nt = 0; nt < 8; nt++) {
            int m = m0 + warpM + mt * 16 + mrow;
            int n = n0 + warpN + nt * 8 + ncol;
            *(float2*)&g_H[(size_t)m * D_ + n]       = make_float2(acc[mt][nt][0], acc[mt][nt][1]);
            *(float2*)&g_H[(size_t)(m + 8) * D_ + n] = make_float2(acc[mt][nt][2], acc[mt][nt][3]);
        }
}

// ---------------- BN stats: deterministic two-stage reduction --------------
__global__ void bn_partial_kernel() {
    int d = threadIdx.x;                 // 0..255
    int blk = blockIdx.x;                // 0..391
    const float* p = g_H + (size_t)blk * 128 * D_ + d;
    float s = 0.f, q = 0.f;
#pragma unroll 4
    for (int r = 0; r < 128; r++) {
        float v = p[(size_t)r * D_];
        s += v;
        q += v * v;
    }
    g_psum[blk * D_ + d] = s;
    g_psq [blk * D_ + d] = q;
}

__global__ void bn_final_kernel() {
    int d = blockIdx.x;                  // 0..255
    int tid = threadIdx.x;               // 0..127
    double s = 0.0, q = 0.0;
    for (int b = tid; b < NBLK_M; b += 128) {
        s += (double)g_psum[b * D_ + d];
        q += (double)g_psq [b * D_ + d];
    }
#pragma unroll
    for (int o = 16; o > 0; o >>= 1) {
        s += __shfl_down_sync(0xffffffffu, s, o);
        q += __shfl_down_sync(0xffffffffu, q, o);
    }
    __shared__ double sh[8];
    int w = tid >> 5;
    if ((tid & 31) == 0) { sh[w] = s; sh[4 + w] = q; }
    __syncthreads();
    if (tid == 0) {
        s = sh[0] + sh[1] + sh[2] + sh[3];
        q = sh[4] + sh[5] + sh[6] + sh[7];
        double m = s / (double)M_;
        double var = q / (double)M_ - m * m;
        g_mean[d]   = (float)m;
        g_invstd[d] = (float)(1.0 / sqrt(var + 1e-5));
    }
}

// ---------------- BN + LIF + PE + LIF fused over T -------------------------
__global__ void lif_kernel(const float* __restrict__ gamma,
                           const float* __restrict__ beta,
                           float* __restrict__ out) {
    int e = blockIdx.x * blockDim.x + threadIdx.x;
    if (e >= BND) return;
    int d = e & (D_ - 1);
    int bn = e >> 8;
    int n = bn % N_;

    float mu = g_mean[d];
    float is = g_invstd[d];
    float g  = gamma[d];
    float bt = beta[d];
    float p  = g_pe[n * D_ + d];

    float v1 = 0.f, v2 = 0.f;
#pragma unroll
    for (int t = 0; t < T_; t++) {
        float h = g_H[(size_t)t * BND + e];
        h = (h - mu) * is;
        h = h * g + bt;
        v1 = v1 + (h - v1) * 0.5f;
        float s1 = ((v1 - 0.5f) >= 0.f) ? 1.f : 0.f;
        v1 = v1 * (1.f - s1);
        float x2 = s1 + p;
        v2 = v2 + (x2 - v2) * 0.5f;
        float s2 = ((v2 - 0.5f) >= 0.f) ? 1.f : 0.f;
        v2 = v2 * (1.f - s2);
        out[(size_t)t * BND + e] = s2;
    }
}

// ---------------- launch ----------------------------------------------------
extern "C" void kernel_launch(void* const* d_in, const int* in_sizes, int n_in,
                              void* d_out, int out_size) {
    const float* x     = (const float*)d_in[0];   // [T,B,N,P]
    const float* W     = (const float*)d_in[1];   // [D,P]
    const float* gamma = (const float*)d_in[2];   // [D]
    const float* beta  = (const float*)d_in[3];   // [D]
    float* out = (float*)d_out;                   // [T,B,N,D]

    cudaFuncSetAttribute(gemm_bf16x3,
                         cudaFuncAttributeMaxDynamicSharedMemorySize, SMEM_DYN);

    pe_kernel<<<N_, 128>>>();
    splitB_kernel<<<(int)(SB_ELEMS / 4 / 256), 256>>>(W);   // 192 blocks
    gemm_bf16x3<<<dim3(2, NBLK_M), 256, SMEM_DYN>>>(x);
    bn_partial_kernel<<<NBLK_M, 256>>>();
    bn_final_kernel<<<D_, 128>>>();
    lif_kernel<<<BND / 256, 256>>>(gamma, beta, out);
}

// round 13
// speedup vs baseline: 1.8764x; 1.0471x over previous
#include <cuda_runtime.h>
#include <cuda_bf16.h>
#include <cstdint>
#include <math.h>

// Problem dims (fixed by the dataset)
#define T_  4
#define B_  64
#define N_  196
#define P_  768
#define D_  256
#define M_  (T_ * B_ * N_)        // 50176
#define BND (B_ * N_ * D_)        // 3211264
#define NBLK_M (M_ / 128)         // 392

static constexpr size_t SB_ELEMS = (size_t)D_ * P_;   // 196,608

// ---------------- scratch (allocation-free per harness rules) ----------------
__device__ float g_H[(size_t)M_ * D_];                 // GEMM output [M, D]
__device__ __nv_bfloat16 g_SB[3][SB_ELEMS];            // bf16x3 splits of W
__device__ float g_psum[NBLK_M * D_];
__device__ float g_psq [NBLK_M * D_];
__device__ float g_mean[D_];
__device__ float g_invstd[D_];
__device__ float g_pe[N_ * D_];

// ---------------- tAPE positional encoding --------------------------------
__global__ void pe_kernel() {
    int n = blockIdx.x;          // 0..195
    int i = threadIdx.x;         // 0..127
    const float c = (float)(-9.210340371976184 / 256.0);
    float t = (float)(2 * i) * c;
    float div = (float)exp((double)t);
    float arg = ((float)n * div) * (float)(256.0 / 196.0);
    g_pe[n * D_ + 2 * i]     = (float)sin((double)arg);
    g_pe[n * D_ + 2 * i + 1] = (float)cos((double)arg);
}

// ---------------- fp32 -> bf16 x3 error-free split --------------------------
__device__ __forceinline__ unsigned pack2(unsigned short lo, unsigned short hi) {
    return (unsigned)lo | ((unsigned)hi << 16);
}

__device__ __forceinline__ void split1(float x, unsigned short& o1,
                                       unsigned short& o2, unsigned short& o3) {
    __nv_bfloat16 b1 = __float2bfloat16_rn(x);
    float r = x - __bfloat162float(b1);          // exact
    __nv_bfloat16 b2 = __float2bfloat16_rn(r);
    float r2 = r - __bfloat162float(b2);         // exact
    __nv_bfloat16 b3 = __float2bfloat16_rn(r2);
    o1 = *(unsigned short*)&b1;
    o2 = *(unsigned short*)&b2;
    o3 = *(unsigned short*)&b3;
}

__device__ __forceinline__ void split4(const float4 v,
                                       __nv_bfloat16* p1, __nv_bfloat16* p2, __nv_bfloat16* p3) {
    float xs[4] = {v.x, v.y, v.z, v.w};
    unsigned short a1[4], a2[4], a3[4];
#pragma unroll
    for (int j = 0; j < 4; j++) split1(xs[j], a1[j], a2[j], a3[j]);
    uint2 u1 = {pack2(a1[0], a1[1]), pack2(a1[2], a1[3])};
    uint2 u2 = {pack2(a2[0], a2[1]), pack2(a2[2], a2[3])};
    uint2 u3 = {pack2(a3[0], a3[1]), pack2(a3[2], a3[3])};
    *(uint2*)p1 = u1;
    *(uint2*)p2 = u2;
    *(uint2*)p3 = u3;
}

__global__ void splitB_kernel(const float* __restrict__ w) {
    size_t i = ((size_t)blockIdx.x * 256 + threadIdx.x) * 4;
    float4 v = *(const float4*)(w + i);
    split4(v, &g_SB[0][i], &g_SB[1][i], &g_SB[2][i]);
}

// ---------------- bf16x3 tensor-core GEMM, fused A-split + BN partials -------
// H[m,d] = sum_p x[m,p] * W[d,p], fp32 accuracy via 6 bf16 pairings.
// Mainloop identical to the previous round (bitwise-same H).
#define LDSM4(R, addr) \
    asm volatile("ldmatrix.sync.aligned.m8n8.x4.shared.b16 {%0,%1,%2,%3}, [%4];" \
                 : "=r"(R[0]), "=r"(R[1]), "=r"(R[2]), "=r"(R[3]) : "r"(addr))

#define MMA16816(Dst, A, B0, B1) \
    asm volatile("mma.sync.aligned.m16n8k16.row.col.f32.bf16.bf16.f32 " \
                 "{%0,%1,%2,%3},{%4,%5,%6,%7},{%8,%9},{%0,%1,%2,%3};" \
                 : "+f"(Dst[0]), "+f"(Dst[1]), "+f"(Dst[2]), "+f"(Dst[3]) \
                 : "r"(A[0]), "r"(A[1]), "r"(A[2]), "r"(A[3]), "r"(B0), "r"(B1))

#define CP16(dst, src) \
    asm volatile("cp.async.cg.shared.global [%0], [%1], 16;" :: "r"(dst), "l"(src) : "memory")

// Tiles: 128 rows x 16 cols bf16 = 4KB, row stride 32B (2 x 16B chunks),
// chunk cu stored at cu ^ ((row>>2)&1)  (unchanged layout -> same ldmatrix).
#define TILE_BYTES  4096
#define ABUF_BYTES  (3 * TILE_BYTES)     // one A stage: levels A1,A2,A3
#define BBUF_BYTES  (3 * TILE_BYTES)     // one B stage: levels B1,B2,B3
#define KC 16
#define NST (P_ / KC)        // 48
#define B_OFF (2 * ABUF_BYTES)           // A double-buffered, then B x3
#define STAGE_SMEM (2 * ABUF_BYTES + 3 * BBUF_BYTES)   // 61440
#define COLSTRIDE 132                                  // fp32, bank-conflict-free
#define SMEM_DYN (128 * COLSTRIDE * 4)                 // 67584 (>= STAGE_SMEM)

__global__ void __launch_bounds__(256, 2) gemm_bf16x3(const float* __restrict__ x) {
    extern __shared__ __align__(16) unsigned char smem[];
    const int tid  = threadIdx.x;
    const int lane = tid & 31;
    const int warp = tid >> 5;
    const int warpM = (warp >> 1) * 32;   // 0,32,64,96
    const int warpN = (warp & 1) * 64;    // 0,64
    const int n0 = blockIdx.x * 128;      // n fastest: N-tile pair shares A via L2
    const int m0 = blockIdx.y * 128;

    const uint32_t smem_u32 = (uint32_t)__cvta_generic_to_shared(smem);

    // ---- per-thread A geometry: row = tid>>1, 8-float half h = tid&1
    const int arow = tid >> 1;
    const int ah   = tid & 1;
    const uint32_t asts = (uint32_t)(arow * 32) + (uint32_t)((ah ^ ((arow >> 2) & 1)) << 4);
    const float* axp = x + (size_t)(m0 + arow) * P_ + ah * 8;

    // ---- per-thread B cp.async geometry: one 16B chunk per tile
    const int crow = tid >> 1;
    const int ccu  = tid & 1;
    const uint32_t cdst0 = (uint32_t)(crow * 32) + (uint32_t)((ccu ^ ((crow >> 2) & 1)) << 4);
    const size_t csrcB = (size_t)(n0 + crow) * P_ + ccu * 8;

    // ---- ldmatrix address precompute (within-tile offsets)
    const int rAl = lane & 15;
    const int cxA = lane >> 4;
    uint32_t offA[2];
#pragma unroll
    for (int mt = 0; mt < 2; mt++) {
        int r = warpM + mt * 16 + rAl;
        offA[mt] = (uint32_t)(r * 32) + (uint32_t)(((cxA ^ ((r >> 2) & 1))) << 4);
    }
    const int rBl = (lane & 7) + ((lane >> 4) & 1) * 8;
    const int cxB = (lane >> 3) & 1;
    uint32_t offB[4];
#pragma unroll
    for (int g = 0; g < 4; g++) {
        int r = warpN + g * 16 + rBl;
        offB[g] = (uint32_t)(r * 32) + (uint32_t)(((cxB ^ ((r >> 2) & 1))) << 4);
    }

    float acc[2][8][4];
#pragma unroll
    for (int i = 0; i < 2; i++)
#pragma unroll
        for (int j = 0; j < 8; j++)
#pragma unroll
            for (int k = 0; k < 4; k++) acc[i][j][k] = 0.f;

    // ---- A helpers: LDG 8 floats; split + STS into 3 level tiles
    float4 ra0, ra1;
    auto ldgA = [&](int ks) {
        const float* p = axp + ks * KC;
        ra0 = *(const float4*)p;
        ra1 = *(const float4*)(p + 4);
    };
    auto stsA = [&](int abuf) {
        float xs[8] = {ra0.x, ra0.y, ra0.z, ra0.w, ra1.x, ra1.y, ra1.z, ra1.w};
        unsigned short l1[8], l2[8], l3[8];
#pragma unroll
        for (int j = 0; j < 8; j++) split1(xs[j], l1[j], l2[j], l3[j]);
        unsigned char* base = smem + abuf * ABUF_BYTES + asts;
        *(uint4*)(base)                 = make_uint4(pack2(l1[0], l1[1]), pack2(l1[2], l1[3]),
                                                    pack2(l1[4], l1[5]), pack2(l1[6], l1[7]));
        *(uint4*)(base + TILE_BYTES)    = make_uint4(pack2(l2[0], l2[1]), pack2(l2[2], l2[3]),
                                                    pack2(l2[4], l2[5]), pack2(l2[6], l2[7]));
        *(uint4*)(base + 2 * TILE_BYTES)= make_uint4(pack2(l3[0], l3[1]), pack2(l3[2], l3[3]),
                                                    pack2(l3[4], l3[5]), pack2(l3[6], l3[7]));
    };

    // ---- B stage loader (cp.async, 3 levels, one commit group)
    auto loadB = [&](int ks, int bbuf) {
        const uint32_t so = smem_u32 + (uint32_t)(B_OFF + bbuf * BBUF_BYTES) + cdst0;
        const size_t kof = (size_t)ks * KC;
#pragma unroll
        for (int t = 0; t < 3; t++)
            CP16(so + t * TILE_BYTES,
                 (const char*)(&g_SB[t][0]) + (csrcB + kof) * 2);
        asm volatile("cp.async.commit_group;" ::: "memory");
    };

    // ---- stage compute: identical op order to previous rounds
    auto compute_stage = [&](uint32_t aBase, uint32_t bBase) {
#pragma unroll
        for (int j = 0; j < 3; j++) {
            const uint32_t Bb = bBase + (uint32_t)(j * TILE_BYTES);
            uint32_t bf[4][4];
#pragma unroll
            for (int g = 0; g < 4; g++) LDSM4(bf[g], offB[g] + Bb);
#pragma unroll
            for (int i = 0; i < 3 - j; i++) {          // i + j <= 2
                const uint32_t Ab = aBase + (uint32_t)(i * TILE_BYTES);
                uint32_t a0[4], a1[4];
                LDSM4(a0, offA[0] + Ab);
                LDSM4(a1, offA[1] + Ab);
#pragma unroll
                for (int g = 0; g < 4; g++) {
                    MMA16816(acc[0][2 * g],     a0, bf[g][0], bf[g][1]);
                    MMA16816(acc[0][2 * g + 1], a0, bf[g][2], bf[g][3]);
                    MMA16816(acc[1][2 * g],     a1, bf[g][0], bf[g][1]);
                    MMA16816(acc[1][2 * g + 1], a1, bf[g][2], bf[g][3]);
                }
            }
        }
    };

    // ---- prologue
    loadB(0, 0);
    loadB(1, 1);
    ldgA(0);
    stsA(0);            // A stage 0 -> buffer 0 (published by first sync)
    ldgA(1);

    // ---- mainloop: one barrier per iteration
    for (int it = 0; it < NST; it++) {
        if (it < NST - 1) {
            asm volatile("cp.async.wait_group 1;" ::: "memory");   // B(it) done
        } else {
            asm volatile("cp.async.wait_group 0;" ::: "memory");
        }
        __syncthreads();   // publish B(it) + A-STS(it) ; compute(it-1) drained
        if (it + 1 < NST) stsA((it + 1) & 1);     // buffer (it+1)&1 == (it-1)&1, drained
        if (it + 2 < NST) {
            ldgA(it + 2);
            loadB(it + 2, (it + 2) % 3);          // buffer (it+2)%3 == (it-1)%3, drained
        }
        compute_stage(smem_u32 + (uint32_t)((it & 1) * ABUF_BYTES),
                      smem_u32 + (uint32_t)(B_OFF + (it % 3) * BBUF_BYTES));
    }

    // ---- epilogue 1: fp32 accumulators -> g_H
    const int mrow = lane >> 2;
    const int ncol = (lane & 3) * 2;
#pragma unroll
    for (int mt = 0; mt < 2; mt++)
#pragma unroll
        for (int nt = 0; nt < 8; nt++) {
            int m = m0 + warpM + mt * 16 + mrow;
            int n = n0 + warpN + nt * 8 + ncol;
            *(float2*)&g_H[(size_t)m * D_ + n]       = make_float2(acc[mt][nt][0], acc[mt][nt][1]);
            *(float2*)&g_H[(size_t)(m + 8) * D_ + n] = make_float2(acc[mt][nt][2], acc[mt][nt][3]);
        }

    // ---- epilogue 2: fused BN partials (bitwise-identical to bn_partial).
    // Stage the 128x128 tile column-major in smem, then each column is summed
    // in ascending row order: s via FADD chain, q via FFMA chain (independent
    // accumulators, exactly as the old kernel's loop produced them).
    __syncthreads();               // mainloop smem reads done; safe to reuse
    float* sm = (float*)smem;      // [col][row], stride COLSTRIDE
#pragma unroll
    for (int mt = 0; mt < 2; mt++)
#pragma unroll
        for (int nt = 0; nt < 8; nt++) {
            int r = warpM + mt * 16 + mrow;
            int c = warpN + nt * 8 + ncol;
            sm[c * COLSTRIDE + r]             = acc[mt][nt][0];
            sm[(c + 1) * COLSTRIDE + r]       = acc[mt][nt][1];
            sm[c * COLSTRIDE + r + 8]         = acc[mt][nt][2];
            sm[(c + 1) * COLSTRIDE + r + 8]   = acc[mt][nt][3];
        }
    __syncthreads();
    {
        const int c = tid & 127;
        const float* col = sm + c * COLSTRIDE;
        if (tid < 128) {
            float s = 0.f;
#pragma unroll 4
            for (int r = 0; r < 128; r++) s += col[r];
            g_psum[blockIdx.y * D_ + n0 + c] = s;
        } else {
            float q = 0.f;
#pragma unroll 4
            for (int r = 0; r < 128; r++) { float v = col[r]; q += v * v; }
            g_psq[blockIdx.y * D_ + n0 + c] = q;
        }
    }
}

// ---------------- BN stats finalize ----------------------------------------
__global__ void bn_final_kernel() {
    int d = blockIdx.x;                  // 0..255
    int tid = threadIdx.x;               // 0..127
    double s = 0.0, q = 0.0;
    for (int b = tid; b < NBLK_M; b += 128) {
        s += (double)g_psum[b * D_ + d];
        q += (double)g_psq [b * D_ + d];
    }
#pragma unroll
    for (int o = 16; o > 0; o >>= 1) {
        s += __shfl_down_sync(0xffffffffu, s, o);
        q += __shfl_down_sync(0xffffffffu, q, o);
    }
    __shared__ double sh[8];
    int w = tid >> 5;
    if ((tid & 31) == 0) { sh[w] = s; sh[4 + w] = q; }
    __syncthreads();
    if (tid == 0) {
        s = sh[0] + sh[1] + sh[2] + sh[3];
        q = sh[4] + sh[5] + sh[6] + sh[7];
        double m = s / (double)M_;
        double var = q / (double)M_ - m * m;
        g_mean[d]   = (float)m;
        g_invstd[d] = (float)(1.0 / sqrt(var + 1e-5));
    }
}

// ---------------- BN + LIF + PE + LIF fused over T, float4 -----------------
__global__ void lif_kernel(const float* __restrict__ gamma,
                           const float* __restrict__ beta,
                           float* __restrict__ out) {
    int e4 = blockIdx.x * blockDim.x + threadIdx.x;    // BND/4 threads
    int d4 = (e4 & 63) * 4;        // 64 float4-groups per D
    int bn = e4 >> 6;
    int n = bn % N_;

    float4 mu = *(const float4*)&g_mean[d4];
    float4 is = *(const float4*)&g_invstd[d4];
    float4 g  = *(const float4*)&gamma[d4];
    float4 bt = *(const float4*)&beta[d4];
    float4 p  = *(const float4*)&g_pe[n * D_ + d4];

    float v1[4] = {0.f, 0.f, 0.f, 0.f};
    float v2[4] = {0.f, 0.f, 0.f, 0.f};
    const float* muv = &mu.x; const float* isv = &is.x;
    const float* gv  = &g.x;  const float* btv = &bt.x;
    const float* pv  = &p.x;

#pragma unroll
    for (int t = 0; t < T_; t++) {
        float4 hh = *(const float4*)&g_H[(size_t)t * BND + (size_t)e4 * 4];
        float h[4] = {hh.x, hh.y, hh.z, hh.w};
        float s2o[4];
#pragma unroll
        for (int k = 0; k < 4; k++) {
            float hv = (h[k] - muv[k]) * isv[k];
            hv = hv * gv[k] + btv[k];
            v1[k] = v1[k] + (hv - v1[k]) * 0.5f;
            float s1 = ((v1[k] - 0.5f) >= 0.f) ? 1.f : 0.f;
            v1[k] = v1[k] * (1.f - s1);
            float x2 = s1 + pv[k];
            v2[k] = v2[k] + (x2 - v2[k]) * 0.5f;
            float s2 = ((v2[k] - 0.5f) >= 0.f) ? 1.f : 0.f;
            v2[k] = v2[k] * (1.f - s2);
            s2o[k] = s2;
        }
        *(float4*)&out[(size_t)t * BND + (size_t)e4 * 4] =
            make_float4(s2o[0], s2o[1], s2o[2], s2o[3]);
    }
}

// ---------------- launch ----------------------------------------------------
extern "C" void kernel_launch(void* const* d_in, const int* in_sizes, int n_in,
                              void* d_out, int out_size) {
    const float* x     = (const float*)d_in[0];   // [T,B,N,P]
    const float* W     = (const float*)d_in[1];   // [D,P]
    const float* gamma = (const float*)d_in[2];   // [D]
    const float* beta  = (const float*)d_in[3];   // [D]
    float* out = (float*)d_out;                   // [T,B,N,D]

    cudaFuncSetAttribute(gemm_bf16x3,
                         cudaFuncAttributeMaxDynamicSharedMemorySize, SMEM_DYN);

    pe_kernel<<<N_, 128>>>();
    splitB_kernel<<<(int)(SB_ELEMS / 4 / 256), 256>>>(W);   // 192 blocks
    gemm_bf16x3<<<dim3(2, NBLK_M), 256, SMEM_DYN>>>(x);
    bn_final_kernel<<<D_, 128>>>();
    lif_kernel<<<BND / 4 / 256, 256>>>(gamma, beta, out);
}